// round 5
// baseline (speedup 1.0000x reference)
#include <cuda_runtime.h>
#include <cuda_bf16.h>
#include <cstdint>

// ---------------- problem constants ----------------
constexpr int B_ROWS = 16384;
constexpr int D      = 2048;
constexpr int N_TOP  = 8;
constexpr int N_CLS  = 16;
constexpr int N_OUT  = 128;
constexpr int NC     = 136;          // 8 top + 128 bottom
constexpr int NTILES = 17;           // 17 x n8
constexpr int KSTEPS = D / 16;       // 128

constexpr int BM      = 128;
constexpr int THREADS = 512;         // 16 warps: wy in [0,4) x 32 rows, wx in [0,4) tiles
constexpr int LPITCH  = 137;

constexpr int STAGE_BYTES = NTILES * 512;   // 8704 B per kstep of packed W
constexpr int STAGE_U4    = NTILES * 32;    // 544 uint4 per stage
constexpr int NSTAGES     = 3;

// Packed weights: per (kstep, tile, lane) uint4 {b0hi, b1hi, b0lo, b1lo}.
__device__ uint4 g_Wp[KSTEPS * STAGE_U4];
__device__ float g_bc[NC];

// ---------------- helpers ----------------
__device__ __forceinline__ void split2(float2 v, uint32_t& hi, uint32_t& lo) {
    __nv_bfloat162 h = __float22bfloat162_rn(v);
    float2 hf = __bfloat1622float2(h);
    __nv_bfloat162 l = __float22bfloat162_rn(make_float2(v.x - hf.x, v.y - hf.y));
    hi = *reinterpret_cast<uint32_t*>(&h);
    lo = *reinterpret_cast<uint32_t*>(&l);
}

#define MMA16816(c, a0, a1, a2, a3, b0, b1) \
    asm volatile("mma.sync.aligned.m16n8k16.row.col.f32.bf16.bf16.f32 " \
        "{%0,%1,%2,%3}, {%4,%5,%6,%7}, {%8,%9}, {%0,%1,%2,%3};" \
        : "+f"((c)[0]), "+f"((c)[1]), "+f"((c)[2]), "+f"((c)[3]) \
        : "r"(a0), "r"(a1), "r"(a2), "r"(a3), "r"(b0), "r"(b1))

__device__ __forceinline__ void cpa16(uint32_t dst, const void* src) {
    asm volatile("cp.async.cg.shared.global [%0], [%1], 16;" :: "r"(dst), "l"(src));
}
#define CPA_COMMIT() asm volatile("cp.async.commit_group;" ::: "memory")
#define CPA_WAIT(n)  asm volatile("cp.async.wait_group %0;" :: "n"(n) : "memory")

__device__ __forceinline__ uint32_t smem_u32(const void* p) {
    uint32_t a;
    asm("{ .reg .u64 t; cvta.to.shared.u64 t, %1; cvt.u32.u64 %0, t; }" : "=r"(a) : "l"(p));
    return a;
}

// ---------------------------------------------------------------------------
// Pack W into per-lane fragment layout (same as R4).
// ---------------------------------------------------------------------------
__device__ __forceinline__ float wval(const float* __restrict__ topW,
                                      const float* __restrict__ botW,
                                      int n, int k) {
    if (n < N_TOP) return topW[n * D + k];
    int m = n - 8;
    return botW[((m >> 4) * D + k) * N_CLS + (m & 15)];
}

__global__ void pack_kernel(const float* __restrict__ topW,
                            const float* __restrict__ topb,
                            const float* __restrict__ botW,
                            const float* __restrict__ botb) {
    int idx = blockIdx.x * blockDim.x + threadIdx.x;
    if (idx < NC) g_bc[idx] = (idx < N_TOP) ? topb[idx] : botb[idx - 8];
    if (idx >= KSTEPS * STAGE_U4) return;

    int lane = idx & 31;
    int t    = (idx >> 5) % NTILES;
    int s    = idx / STAGE_U4;
    int g = lane >> 2, q = lane & 3;
    int n = t * 8 + g;
    int k = s * 16 + 2 * q;

    float x0 = wval(topW, botW, n, k);
    float x1 = wval(topW, botW, n, k + 1);
    float x2 = wval(topW, botW, n, k + 8);
    float x3 = wval(topW, botW, n, k + 9);

    uint32_t h0, l0, h1, l1;
    split2(make_float2(x0, x1), h0, l0);
    split2(make_float2(x2, x3), h1, l1);
    g_Wp[idx] = make_uint4(h0, h1, l0, l1);
}

// ---------------------------------------------------------------------------
// Main kernel: cp.async-pipelined B, register-prefetched A, split-bf16 HMMA.
// ---------------------------------------------------------------------------
__global__ __launch_bounds__(THREADS, 1)
void hier_mma_kernel(const float* __restrict__ A, float* __restrict__ out) {
    extern __shared__ char smem_raw[];              // union: B stages | logits
    char* bbuf = smem_raw;
    float* L = reinterpret_cast<float*>(smem_raw);
    const uint32_t sbase = smem_u32(smem_raw);

    const int tid  = threadIdx.x;
    const int lane = tid & 31;
    const int wid  = tid >> 5;
    const int wy   = wid >> 2;                      // 0..3 : 32-row group
    const int wx   = wid & 3;                       // 0..3 : tile group
    const int g    = lane >> 2;
    const int q    = lane & 3;
    const int rowBase = blockIdx.x * BM;

    const int tbase = (wx == 0) ? 0 : (5 + (wx - 1) * 4);
    const int nt    = (wx == 0) ? 5 : 4;

    // A pointer: row rowBase + wy*32 + g, col 2q; row offsets 0/8/16/24, col +8
    const float* pr = A + (size_t)(rowBase + wy * 32 + g) * D + 2 * q;

    float acc[5][8];
#pragma unroll
    for (int t = 0; t < 5; ++t)
#pragma unroll
        for (int j = 0; j < 8; ++j) acc[t][j] = 0.0f;

    // ---- prologue: stage 0,1 B copies in flight; A for kstep 0 ----
#pragma unroll
    for (int st = 0; st < 2; ++st) {
        for (int u = tid; u < STAGE_U4; u += THREADS)
            cpa16(sbase + st * STAGE_BYTES + u * 16, g_Wp + (size_t)st * STAGE_U4 + u);
        CPA_COMMIT();
    }

    float2 xr[8];
#pragma unroll
    for (int h = 0; h < 2; ++h) {
        const float* p = pr + (size_t)h * 16 * D;
        xr[h * 4 + 0] = *reinterpret_cast<const float2*>(p);
        xr[h * 4 + 1] = *reinterpret_cast<const float2*>(p + 8 * D);
        xr[h * 4 + 2] = *reinterpret_cast<const float2*>(p + 8);
        xr[h * 4 + 3] = *reinterpret_cast<const float2*>(p + 8 * D + 8);
    }

    for (int s = 0; s < KSTEPS; ++s) {
        CPA_WAIT(1);                 // stage s copies (mine) complete
        __syncthreads();             // everyone's complete & visible; prev reads done

        // issue stage s+2 (safe: all readers of this slot finished before barrier)
        if (s + 2 < KSTEPS) {
            int slot = (s + 2) % NSTAGES;
            for (int u = tid; u < STAGE_U4; u += THREADS)
                cpa16(sbase + slot * STAGE_BYTES + u * 16,
                      g_Wp + (size_t)(s + 2) * STAGE_U4 + u);
        }
        CPA_COMMIT();

        // split current A, then prefetch next kstep's A
        uint32_t ahi[8], alo[8];
#pragma unroll
        for (int j = 0; j < 8; ++j) split2(xr[j], ahi[j], alo[j]);
        if (s + 1 < KSTEPS) {
            const float* pk = pr + (size_t)(s + 1) * 16;
#pragma unroll
            for (int h = 0; h < 2; ++h) {
                const float* p = pk + (size_t)h * 16 * D;
                xr[h * 4 + 0] = *reinterpret_cast<const float2*>(p);
                xr[h * 4 + 1] = *reinterpret_cast<const float2*>(p + 8 * D);
                xr[h * 4 + 2] = *reinterpret_cast<const float2*>(p + 8);
                xr[h * 4 + 3] = *reinterpret_cast<const float2*>(p + 8 * D + 8);
            }
        }

        // compute: nt tiles, 6 MMAs each (2 row-halves x {hi*hi, lo*hi, hi*lo})
        const char* bp = bbuf + (s % NSTAGES) * STAGE_BYTES + lane * 16;
        uint4 b = *reinterpret_cast<const uint4*>(bp + (size_t)tbase * 512);
#pragma unroll
        for (int tt = 0; tt < 5; ++tt) {
            if (tt < nt) {
                uint4 bn = (tt + 1 < nt)
                    ? *reinterpret_cast<const uint4*>(bp + (size_t)(tbase + tt + 1) * 512)
                    : b;
                MMA16816(acc[tt],     ahi[0], ahi[1], ahi[2], ahi[3], b.x, b.y);
                MMA16816(acc[tt],     alo[0], alo[1], alo[2], alo[3], b.x, b.y);
                MMA16816(acc[tt],     ahi[0], ahi[1], ahi[2], ahi[3], b.z, b.w);
                MMA16816(acc[tt] + 4, ahi[4], ahi[5], ahi[6], ahi[7], b.x, b.y);
                MMA16816(acc[tt] + 4, alo[4], alo[5], alo[6], alo[7], b.x, b.y);
                MMA16816(acc[tt] + 4, ahi[4], ahi[5], ahi[6], ahi[7], b.z, b.w);
                b = bn;
            }
        }
    }

    __syncthreads();   // done with B buffers; smem becomes logits

    // ---- stage logits (+bias) into smem ----
#pragma unroll
    for (int tt = 0; tt < 5; ++tt) {
        if (tt < nt) {
            int c = (tbase + tt) * 8 + 2 * q;
            float b0 = g_bc[c], b1 = g_bc[c + 1];
#pragma unroll
            for (int h = 0; h < 2; ++h) {
                int r = wy * 32 + h * 16 + g;
                L[r * LPITCH + c]           = acc[tt][4 * h + 0] + b0;
                L[r * LPITCH + c + 1]       = acc[tt][4 * h + 1] + b1;
                L[(r + 8) * LPITCH + c]     = acc[tt][4 * h + 2] + b0;
                L[(r + 8) * LPITCH + c + 1] = acc[tt][4 * h + 3] + b1;
            }
        }
    }
    __syncthreads();

    // ---- per-row: sigmoid gate + 8x softmax(16), in place ----
    if (tid < BM) {
        float* Lr = L + tid * LPITCH;
#pragma unroll
        for (int t = 0; t < N_TOP; ++t) {
            float gate = 1.0f / (1.0f + __expf(-Lr[t]));
            float* gr = Lr + 8 + t * N_CLS;
            float m = gr[0];
#pragma unroll
            for (int c = 1; c < N_CLS; ++c) m = fmaxf(m, gr[c]);
            float e[N_CLS];
            float sum = 0.0f;
#pragma unroll
            for (int c = 0; c < N_CLS; ++c) { e[c] = __expf(gr[c] - m); sum += e[c]; }
            float inv = gate / sum;
#pragma unroll
            for (int c = 0; c < N_CLS; ++c) gr[c] = e[c] * inv;
        }
    }
    __syncthreads();

    // ---- coalesced writeback 128x128 ----
    for (int idx = tid; idx < BM * N_OUT; idx += THREADS) {
        int r = idx >> 7, c = idx & 127;
        out[(size_t)(rowBase + r) * N_OUT + c] = L[r * LPITCH + 8 + c];
    }
}

// ---------------------------------------------------------------------------
extern "C" void kernel_launch(void* const* d_in, const int* in_sizes, int n_in,
                              void* d_out, int out_size) {
    const float* features = (const float*)d_in[0];
    const float* top_W    = (const float*)d_in[1];
    const float* top_b    = (const float*)d_in[2];
    const float* bottom_W = (const float*)d_in[3];
    const float* bottom_b = (const float*)d_in[4];
    float* out = (float*)d_out;

    {
        int total = KSTEPS * STAGE_U4;
        int threads = 256;
        pack_kernel<<<(total + threads - 1) / threads, threads>>>(
            top_W, top_b, bottom_W, bottom_b);
    }
    constexpr int SMEM_B = NSTAGES * STAGE_BYTES;          // 26112
    constexpr int SMEM_L = BM * LPITCH * (int)sizeof(float); // 70144
    constexpr int SMEM = (SMEM_B > SMEM_L) ? SMEM_B : SMEM_L;
    cudaFuncSetAttribute(hier_mma_kernel,
                         cudaFuncAttributeMaxDynamicSharedMemorySize, SMEM);
    hier_mma_kernel<<<B_ROWS / BM, THREADS, SMEM>>>(features, out);
}

// round 6
// speedup vs baseline: 1.4131x; 1.4131x over previous
#include <cuda_runtime.h>
#include <cuda_bf16.h>
#include <cstdint>

// ---------------- problem constants ----------------
constexpr int B_ROWS = 16384;
constexpr int D      = 2048;
constexpr int N_TOP  = 8;
constexpr int N_CLS  = 16;
constexpr int N_OUT  = 128;
constexpr int NC     = 136;          // 8 top + 128 bottom
constexpr int NTILES = 17;           // 17 x n8
constexpr int KSTEPS = D / 16;       // 128

constexpr int BM      = 128;
constexpr int THREADS = 512;         // 16 warps: wy=wid&3 (32 rows), wx=wid>>2 (tiles)
constexpr int LPITCH  = 137;
constexpr int STEP_U4 = NTILES * 32; // 544 uint4 per kstep

// Packed weights, fragment layout with k-permutation:
// lane(g=lane>>2, q=lane&3) of tile t, kstep s holds
//   b0 = {W[n][k0], W[n][k0+1]}, b1 = {W[n][k0+2], W[n][k0+3]},  n=t*8+g, k0=s*16+4q
// as uint4 {b0hi, b1hi, b0lo, b1lo}.
__device__ uint4 g_Wp[KSTEPS * STEP_U4];
__device__ float g_bc[NC];

// ---------------- helpers ----------------
__device__ __forceinline__ void split2(float x, float y, uint32_t& hi, uint32_t& lo) {
    __nv_bfloat162 h = __float22bfloat162_rn(make_float2(x, y));
    float2 hf = __bfloat1622float2(h);
    __nv_bfloat162 l = __float22bfloat162_rn(make_float2(x - hf.x, y - hf.y));
    hi = *reinterpret_cast<uint32_t*>(&h);
    lo = *reinterpret_cast<uint32_t*>(&l);
}

#define MMA16816(c, a0, a1, a2, a3, b0, b1) \
    asm volatile("mma.sync.aligned.m16n8k16.row.col.f32.bf16.bf16.f32 " \
        "{%0,%1,%2,%3}, {%4,%5,%6,%7}, {%8,%9}, {%0,%1,%2,%3};" \
        : "+f"((c)[0]), "+f"((c)[1]), "+f"((c)[2]), "+f"((c)[3]) \
        : "r"(a0), "r"(a1), "r"(a2), "r"(a3), "r"(b0), "r"(b1))

// ---------------------------------------------------------------------------
// Pack W (k-permuted fragment layout).
// ---------------------------------------------------------------------------
__device__ __forceinline__ float wval(const float* __restrict__ topW,
                                      const float* __restrict__ botW,
                                      int n, int k) {
    if (n < N_TOP) return topW[n * D + k];
    int m = n - 8;
    return botW[((m >> 4) * D + k) * N_CLS + (m & 15)];
}

__global__ void pack_kernel(const float* __restrict__ topW,
                            const float* __restrict__ topb,
                            const float* __restrict__ botW,
                            const float* __restrict__ botb) {
    int idx = blockIdx.x * blockDim.x + threadIdx.x;
    if (idx < NC) g_bc[idx] = (idx < N_TOP) ? topb[idx] : botb[idx - 8];
    if (idx >= KSTEPS * STEP_U4) return;

    int lane = idx & 31;
    int t    = (idx >> 5) % NTILES;
    int s    = idx / STEP_U4;
    int g = lane >> 2, q = lane & 3;
    int n  = t * 8 + g;
    int k0 = s * 16 + 4 * q;

    float x0 = wval(topW, botW, n, k0);
    float x1 = wval(topW, botW, n, k0 + 1);
    float x2 = wval(topW, botW, n, k0 + 2);
    float x3 = wval(topW, botW, n, k0 + 3);

    uint32_t h01, l01, h23, l23;
    split2(x0, x1, h01, l01);
    split2(x2, x3, h23, l23);
    g_Wp[idx] = make_uint4(h01, h23, l01, l23);
}

// ---------------------------------------------------------------------------
// Main kernel: barrier-free split-bf16 HMMA GEMM + gate/softmax epilogue.
// ---------------------------------------------------------------------------
__global__ __launch_bounds__(THREADS, 1)
void hier_mma_kernel(const float* __restrict__ A, float* __restrict__ out) {
    extern __shared__ float L[];            // [128][137] logits
    const int tid  = threadIdx.x;
    const int lane = tid & 31;
    const int wid  = tid >> 5;
    const int wy   = wid & 3;               // 32-row group; spreads across SMSPs? no:
    const int wx   = wid >> 2;              // tile group -> one per SMSP set? see note:
    // NOTE: SMSP = wid & 3 = wy. Each SMSP hosts warps wx=0..3 -> tile work (5+4+4+4=17)
    // identical per SMSP: tensor load balanced.
    const int g    = lane >> 2;
    const int q    = lane & 3;
    const int rowBase = blockIdx.x * BM;

    const int tbase = (wx == 0) ? 0 : (5 + (wx - 1) * 4);
    const int nt    = (wx == 0) ? 5 : 4;

    // A: rows rowBase + wy*32 + g + {0,8,16,24}, col 4q (+16 per kstep)
    const float* ap = A + (size_t)(rowBase + wy * 32 + g) * D + 4 * q;

    float acc[5][8];
#pragma unroll
    for (int t = 0; t < 5; ++t)
#pragma unroll
        for (int j = 0; j < 8; ++j) acc[t][j] = 0.0f;

    const uint4* wp = g_Wp + (size_t)tbase * 32 + lane;

    // ---- prologue: kstep 0 ----
    float4 xr[4];
#pragma unroll
    for (int r = 0; r < 4; ++r)
        xr[r] = *reinterpret_cast<const float4*>(ap + (size_t)r * 8 * D);
    uint4 bc[5];
#pragma unroll
    for (int tt = 0; tt < 5; ++tt)
        if (tt < nt) bc[tt] = wp[tt * 32];

#pragma unroll 2
    for (int s = 0; s < KSTEPS; ++s) {
        // split A into hi/lo fragments: idx 2r+p (r=row 0..3, p=pair 0..1)
        uint32_t ahi[8], alo[8];
#pragma unroll
        for (int r = 0; r < 4; ++r) {
            split2(xr[r].x, xr[r].y, ahi[2 * r],     alo[2 * r]);
            split2(xr[r].z, xr[r].w, ahi[2 * r + 1], alo[2 * r + 1]);
        }

        // prefetch next kstep A (in flight during MMAs)
        if (s + 1 < KSTEPS) {
            const float* apn = ap + (size_t)(s + 1) * 16;
#pragma unroll
            for (int r = 0; r < 4; ++r)
                xr[r] = *reinterpret_cast<const float4*>(apn + (size_t)r * 8 * D);
        }

        // 6 MMAs per tile: 2 row-halves x {hi*hi, lo*hi, hi*lo}
#pragma unroll
        for (int tt = 0; tt < 5; ++tt) {
            if (tt < nt) {
                uint4 b = bc[tt];
                MMA16816(acc[tt],     ahi[0], ahi[2], ahi[1], ahi[3], b.x, b.y);
                MMA16816(acc[tt],     alo[0], alo[2], alo[1], alo[3], b.x, b.y);
                MMA16816(acc[tt],     ahi[0], ahi[2], ahi[1], ahi[3], b.z, b.w);
                MMA16816(acc[tt] + 4, ahi[4], ahi[6], ahi[5], ahi[7], b.x, b.y);
                MMA16816(acc[tt] + 4, alo[4], alo[6], alo[5], alo[7], b.x, b.y);
                MMA16816(acc[tt] + 4, ahi[4], ahi[6], ahi[5], ahi[7], b.z, b.w);
            }
        }

        // reload B for next kstep (latency covered by next iter's split + A issue)
        if (s + 1 < KSTEPS) {
            const uint4* wn = wp + (size_t)(s + 1) * STEP_U4;
#pragma unroll
            for (int tt = 0; tt < 5; ++tt)
                if (tt < nt) bc[tt] = wn[tt * 32];
        }
    }

    // ---- stage logits (+bias) into smem ----
#pragma unroll
    for (int tt = 0; tt < 5; ++tt) {
        if (tt < nt) {
            int c = (tbase + tt) * 8 + 2 * q;
            float b0 = g_bc[c], b1 = g_bc[c + 1];
#pragma unroll
            for (int h = 0; h < 2; ++h) {
                int r = wy * 32 + h * 16 + g;
                L[r * LPITCH + c]           = acc[tt][4 * h + 0] + b0;
                L[r * LPITCH + c + 1]       = acc[tt][4 * h + 1] + b1;
                L[(r + 8) * LPITCH + c]     = acc[tt][4 * h + 2] + b0;
                L[(r + 8) * LPITCH + c + 1] = acc[tt][4 * h + 3] + b1;
            }
        }
    }
    __syncthreads();

    // ---- per-row: sigmoid gate + 8x softmax(16), in place ----
    if (tid < BM) {
        float* Lr = L + tid * LPITCH;
#pragma unroll
        for (int t = 0; t < N_TOP; ++t) {
            float gate = 1.0f / (1.0f + __expf(-Lr[t]));
            float* gr = Lr + 8 + t * N_CLS;
            float m = gr[0];
#pragma unroll
            for (int c = 1; c < N_CLS; ++c) m = fmaxf(m, gr[c]);
            float e[N_CLS];
            float sum = 0.0f;
#pragma unroll
            for (int c = 0; c < N_CLS; ++c) { e[c] = __expf(gr[c] - m); sum += e[c]; }
            float inv = gate / sum;
#pragma unroll
            for (int c = 0; c < N_CLS; ++c) gr[c] = e[c] * inv;
        }
    }
    __syncthreads();

    // ---- coalesced writeback 128x128 ----
    for (int idx = tid; idx < BM * N_OUT; idx += THREADS) {
        int r = idx >> 7, c = idx & 127;
        out[(size_t)(rowBase + r) * N_OUT + c] = L[r * LPITCH + 8 + c];
    }
}

// ---------------------------------------------------------------------------
extern "C" void kernel_launch(void* const* d_in, const int* in_sizes, int n_in,
                              void* d_out, int out_size) {
    const float* features = (const float*)d_in[0];
    const float* top_W    = (const float*)d_in[1];
    const float* top_b    = (const float*)d_in[2];
    const float* bottom_W = (const float*)d_in[3];
    const float* bottom_b = (const float*)d_in[4];
    float* out = (float*)d_out;

    {
        int total = KSTEPS * STEP_U4;
        int threads = 256;
        pack_kernel<<<(total + threads - 1) / threads, threads>>>(
            top_W, top_b, bottom_W, bottom_b);
    }
    constexpr int SMEM = BM * LPITCH * (int)sizeof(float);   // 70144
    cudaFuncSetAttribute(hier_mma_kernel,
                         cudaFuncAttributeMaxDynamicSharedMemorySize, SMEM);
    hier_mma_kernel<<<B_ROWS / BM, THREADS, SMEM>>>(features, out);
}

// round 7
// speedup vs baseline: 1.4975x; 1.0597x over previous
#include <cuda_runtime.h>
#include <cuda_bf16.h>
#include <cstdint>

// ---------------- problem constants ----------------
constexpr int B_ROWS = 16384;
constexpr int D      = 2048;
constexpr int N_TOP  = 8;
constexpr int N_CLS  = 16;
constexpr int N_OUT  = 128;
constexpr int NC     = 136;          // 8 top + 128 bottom
constexpr int NTILES = 17;           // 17 x n8
constexpr int KSTEPS = D / 16;       // 128

constexpr int BM      = 128;
constexpr int THREADS = 512;         // 16 warps: wy=wid&3 (rows), wx=wid>>2 (tiles)
constexpr int LPITCH  = 137;
constexpr int STEP_U4 = NTILES * 32; // 544 uint4 per kstep

// Packed weights, fragment layout with k-permutation:
// lane(g=lane>>2, q=lane&3) of tile t, kstep s holds cols 4q..4q+3 of n=t*8+g
// as uint4 {b01hi, b23hi, b01lo, b23lo}.
__device__ uint4 g_Wp[KSTEPS * STEP_U4];
__device__ float g_bc[NC];

// ---------------- helpers ----------------
// rn split (pack kernel only; one-time cost, best W accuracy)
__device__ __forceinline__ void rsplit2(float x, float y, uint32_t& hi, uint32_t& lo) {
    __nv_bfloat162 h = __float22bfloat162_rn(make_float2(x, y));
    float2 hf = __bfloat1622float2(h);
    __nv_bfloat162 l = __float22bfloat162_rn(make_float2(x - hf.x, y - hf.y));
    hi = *reinterpret_cast<uint32_t*>(&h);
    lo = *reinterpret_cast<uint32_t*>(&l);
}
// truncation split (main loop): hi via PRMT (exact bf16, no cvt), 1 cvt for lo pair
__device__ __forceinline__ void tsplit2(float x, float y, uint32_t& hi, uint32_t& lo) {
    uint32_t xu = __float_as_uint(x), yu = __float_as_uint(y);
    hi = __byte_perm(xu, yu, 0x7632);
    float lx = x - __uint_as_float(xu & 0xFFFF0000u);
    float ly = y - __uint_as_float(yu & 0xFFFF0000u);
    __nv_bfloat162 l = __float22bfloat162_rn(make_float2(lx, ly));
    lo = *reinterpret_cast<uint32_t*>(&l);
}

#define MMA16816(c, a0, a1, a2, a3, b0, b1) \
    asm volatile("mma.sync.aligned.m16n8k16.row.col.f32.bf16.bf16.f32 " \
        "{%0,%1,%2,%3}, {%4,%5,%6,%7}, {%8,%9}, {%0,%1,%2,%3};" \
        : "+f"((c)[0]), "+f"((c)[1]), "+f"((c)[2]), "+f"((c)[3]) \
        : "r"(a0), "r"(a1), "r"(a2), "r"(a3), "r"(b0), "r"(b1))

// 6 MMAs for one n8 tile, alternating accumulator halves
#define TILE6(acc, ahi, alo, b) do { \
    MMA16816((acc),     (ahi)[0], (ahi)[2], (ahi)[1], (ahi)[3], (b).x, (b).y); \
    MMA16816((acc) + 4, (ahi)[4], (ahi)[6], (ahi)[5], (ahi)[7], (b).x, (b).y); \
    MMA16816((acc),     (alo)[0], (alo)[2], (alo)[1], (alo)[3], (b).x, (b).y); \
    MMA16816((acc) + 4, (alo)[4], (alo)[6], (alo)[5], (alo)[7], (b).x, (b).y); \
    MMA16816((acc),     (ahi)[0], (ahi)[2], (ahi)[1], (ahi)[3], (b).z, (b).w); \
    MMA16816((acc) + 4, (ahi)[4], (ahi)[6], (ahi)[5], (ahi)[7], (b).z, (b).w); \
} while (0)

// ---------------------------------------------------------------------------
// Pack W (k-permuted fragment layout), rn split.
// ---------------------------------------------------------------------------
__device__ __forceinline__ float wval(const float* __restrict__ topW,
                                      const float* __restrict__ botW,
                                      int n, int k) {
    if (n < N_TOP) return topW[n * D + k];
    int m = n - 8;
    return botW[((m >> 4) * D + k) * N_CLS + (m & 15)];
}

__global__ void pack_kernel(const float* __restrict__ topW,
                            const float* __restrict__ topb,
                            const float* __restrict__ botW,
                            const float* __restrict__ botb) {
    int idx = blockIdx.x * blockDim.x + threadIdx.x;
    if (idx < NC) g_bc[idx] = (idx < N_TOP) ? topb[idx] : botb[idx - 8];
    if (idx >= KSTEPS * STEP_U4) return;

    int lane = idx & 31;
    int t    = (idx >> 5) % NTILES;
    int s    = idx / STEP_U4;
    int g = lane >> 2, q = lane & 3;
    int n  = t * 8 + g;
    int k0 = s * 16 + 4 * q;

    float x0 = wval(topW, botW, n, k0);
    float x1 = wval(topW, botW, n, k0 + 1);
    float x2 = wval(topW, botW, n, k0 + 2);
    float x3 = wval(topW, botW, n, k0 + 3);

    uint32_t h01, l01, h23, l23;
    rsplit2(x0, x1, h01, l01);
    rsplit2(x2, x3, h23, l23);
    g_Wp[idx] = make_uint4(h01, h23, l01, l23);
}

// ---------------------------------------------------------------------------
// Main kernel: barrier-free split-bf16 HMMA GEMM + gate/softmax epilogue.
// Warp (wy=wid&3, wx=wid>>2): rows wy*32..+31; tiles wx*4..+3 (+tile 16 if wx==0).
// ---------------------------------------------------------------------------
__global__ __launch_bounds__(THREADS, 1)
void hier_mma_kernel(const float* __restrict__ A, float* __restrict__ out) {
    extern __shared__ float L[];            // [128][137] logits
    const int tid  = threadIdx.x;
    const int lane = tid & 31;
    const int wid  = tid >> 5;
    const int wy   = wid & 3;               // SMSP id too -> wx spread per SMSP
    const int wx   = wid >> 2;
    const int g    = lane >> 2;
    const int q    = lane & 3;
    const int rowBase = blockIdx.x * BM;

    const int  tbase = wx * 4;
    const bool extra = (wx == 0);           // tile 16

    // A: rows rowBase + wy*32 + g + {0,8,16,24}, cols 4q.. (+16 per kstep)
    const float* ap = A + (size_t)(rowBase + wy * 32 + g) * D + 4 * q;

    float acc[4][8], accE[8];
#pragma unroll
    for (int t = 0; t < 4; ++t)
#pragma unroll
        for (int j = 0; j < 8; ++j) acc[t][j] = 0.0f;
#pragma unroll
    for (int j = 0; j < 8; ++j) accE[j] = 0.0f;

    const uint4* wp  = g_Wp + (size_t)tbase * 32 + lane;
    const uint4* wpE = g_Wp + (size_t)16 * 32 + lane;

    // ---- prologue: kstep 0 ----
    float4 xr[4];
#pragma unroll
    for (int r = 0; r < 4; ++r)
        xr[r] = *reinterpret_cast<const float4*>(ap + (size_t)r * 8 * D);
    uint4 bc[4], bcE;
#pragma unroll
    for (int tt = 0; tt < 4; ++tt) bc[tt] = wp[tt * 32];
    if (extra) bcE = *wpE;

#pragma unroll 2
    for (int s = 0; s < KSTEPS; ++s) {
        // split A into hi/lo fragments (truncation split: 1 prmt + 1 cvt per pair)
        uint32_t ahi[8], alo[8];
#pragma unroll
        for (int r = 0; r < 4; ++r) {
            tsplit2(xr[r].x, xr[r].y, ahi[2 * r],     alo[2 * r]);
            tsplit2(xr[r].z, xr[r].w, ahi[2 * r + 1], alo[2 * r + 1]);
        }

        // prefetch next kstep A (in flight during MMAs)
        if (s + 1 < KSTEPS) {
            const float* apn = ap + (size_t)(s + 1) * 16;
#pragma unroll
            for (int r = 0; r < 4; ++r)
                xr[r] = *reinterpret_cast<const float4*>(apn + (size_t)r * 8 * D);
        }

        // 24 MMAs over 4 tiles (+6 for the extra tile on wx==0 warps)
#pragma unroll
        for (int tt = 0; tt < 4; ++tt) TILE6(acc[tt], ahi, alo, bc[tt]);
        if (extra) TILE6(accE, ahi, alo, bcE);

        // reload B for next kstep (rolled pointers)
        if (s + 1 < KSTEPS) {
            wp += STEP_U4;
#pragma unroll
            for (int tt = 0; tt < 4; ++tt) bc[tt] = wp[tt * 32];
            if (extra) { wpE += STEP_U4; bcE = *wpE; }
        }
    }

    // ---- stage logits (+bias) into smem ----
#pragma unroll
    for (int tt = 0; tt < 5; ++tt) {
        const float* ac;
        int t;
        if (tt < 4) { ac = acc[tt]; t = tbase + tt; }
        else if (extra) { ac = accE; t = 16; }
        else break;
        int c = t * 8 + 2 * q;
        float b0 = g_bc[c], b1 = g_bc[c + 1];
#pragma unroll
        for (int h = 0; h < 2; ++h) {
            int r = wy * 32 + h * 16 + g;
            L[r * LPITCH + c]           = ac[4 * h + 0] + b0;
            L[r * LPITCH + c + 1]       = ac[4 * h + 1] + b1;
            L[(r + 8) * LPITCH + c]     = ac[4 * h + 2] + b0;
            L[(r + 8) * LPITCH + c + 1] = ac[4 * h + 3] + b1;
        }
    }
    __syncthreads();

    // ---- per-row: sigmoid gate + 8x softmax(16), in place ----
    if (tid < BM) {
        float* Lr = L + tid * LPITCH;
#pragma unroll
        for (int t = 0; t < N_TOP; ++t) {
            float gate = 1.0f / (1.0f + __expf(-Lr[t]));
            float* gr = Lr + 8 + t * N_CLS;
            float m = gr[0];
#pragma unroll
            for (int c = 1; c < N_CLS; ++c) m = fmaxf(m, gr[c]);
            float e[N_CLS];
            float sum = 0.0f;
#pragma unroll
            for (int c = 0; c < N_CLS; ++c) { e[c] = __expf(gr[c] - m); sum += e[c]; }
            float inv = gate / sum;
#pragma unroll
            for (int c = 0; c < N_CLS; ++c) gr[c] = e[c] * inv;
        }
    }
    __syncthreads();

    // ---- coalesced writeback 128x128 ----
    for (int idx = tid; idx < BM * N_OUT; idx += THREADS) {
        int r = idx >> 7, c = idx & 127;
        out[(size_t)(rowBase + r) * N_OUT + c] = L[r * LPITCH + 8 + c];
    }
}

// ---------------------------------------------------------------------------
extern "C" void kernel_launch(void* const* d_in, const int* in_sizes, int n_in,
                              void* d_out, int out_size) {
    const float* features = (const float*)d_in[0];
    const float* top_W    = (const float*)d_in[1];
    const float* top_b    = (const float*)d_in[2];
    const float* bottom_W = (const float*)d_in[3];
    const float* bottom_b = (const float*)d_in[4];
    float* out = (float*)d_out;

    {
        int total = KSTEPS * STEP_U4;
        int threads = 256;
        pack_kernel<<<(total + threads - 1) / threads, threads>>>(
            top_W, top_b, bottom_W, bottom_b);
    }
    constexpr int SMEM = BM * LPITCH * (int)sizeof(float);   // 70144
    cudaFuncSetAttribute(hier_mma_kernel,
                         cudaFuncAttributeMaxDynamicSharedMemorySize, SMEM);
    hier_mma_kernel<<<B_ROWS / BM, THREADS, SMEM>>>(features, out);
}

// round 8
// speedup vs baseline: 1.5884x; 1.0607x over previous
#include <cuda_runtime.h>
#include <cuda_bf16.h>
#include <cstdint>

// ---------------- problem constants ----------------
constexpr int B_ROWS = 16384;
constexpr int D      = 2048;
constexpr int N_TOP  = 8;
constexpr int N_CLS  = 16;
constexpr int N_OUT  = 128;
constexpr int NC     = 136;          // 8 top + 128 bottom
constexpr int NTILES = 17;           // 17 x n8
constexpr int KSTEPS = D / 16;       // 128

constexpr int BM      = 128;
constexpr int THREADS = 512;         // 16 warps: wy=wid&3 (rows), wx=wid>>2 (tiles)
constexpr int LPITCH  = 137;
constexpr int STEP_U4 = NTILES * 32; // 544 uint4 per kstep

// per-warp private pipeline staging
constexpr int DEPTH   = 3;           // stages; prefetch distance 2
constexpr int A_STAGE = 2048;        // 32 rows x 64B fragments per kstep
constexpr int B_STAGE = 2560;        // 5 tiles x 512B per kstep
constexpr int SMEM_PIPE = 16 * DEPTH * (A_STAGE + B_STAGE);        // 221184
constexpr int SMEM_L    = BM * LPITCH * (int)sizeof(float);        // 70144
constexpr int SMEM      = (SMEM_PIPE > SMEM_L) ? SMEM_PIPE : SMEM_L;

// Packed weights, fragment layout with k-permutation (same as R7):
// lane(g=lane>>2, q=lane&3) of tile t, kstep s holds cols 4q..4q+3 of n=t*8+g
// as uint4 {b01hi, b23hi, b01lo, b23lo}.
__device__ uint4 g_Wp[KSTEPS * STEP_U4];
__device__ float g_bc[NC];

// ---------------- helpers ----------------
__device__ __forceinline__ void rsplit2(float x, float y, uint32_t& hi, uint32_t& lo) {
    __nv_bfloat162 h = __float22bfloat162_rn(make_float2(x, y));
    float2 hf = __bfloat1622float2(h);
    __nv_bfloat162 l = __float22bfloat162_rn(make_float2(x - hf.x, y - hf.y));
    hi = *reinterpret_cast<uint32_t*>(&h);
    lo = *reinterpret_cast<uint32_t*>(&l);
}
__device__ __forceinline__ void tsplit2(float x, float y, uint32_t& hi, uint32_t& lo) {
    uint32_t xu = __float_as_uint(x), yu = __float_as_uint(y);
    hi = __byte_perm(xu, yu, 0x7632);
    float lx = x - __uint_as_float(xu & 0xFFFF0000u);
    float ly = y - __uint_as_float(yu & 0xFFFF0000u);
    __nv_bfloat162 l = __float22bfloat162_rn(make_float2(lx, ly));
    lo = *reinterpret_cast<uint32_t*>(&l);
}

__device__ __forceinline__ uint32_t smem_u32(const void* p) {
    uint32_t a;
    asm("{ .reg .u64 t; cvta.to.shared.u64 t, %1; cvt.u32.u64 %0, t; }" : "=r"(a) : "l"(p));
    return a;
}
__device__ __forceinline__ void cpa16(uint32_t dst, const void* src) {
    asm volatile("cp.async.cg.shared.global [%0], [%1], 16;" :: "r"(dst), "l"(src) : "memory");
}
#define CPA_COMMIT() asm volatile("cp.async.commit_group;" ::: "memory")
#define CPA_WAIT2()  asm volatile("cp.async.wait_group 2;" ::: "memory")

__device__ __forceinline__ float4 lds_f4(uint32_t a) {
    float4 v;
    asm volatile("ld.shared.v4.f32 {%0,%1,%2,%3}, [%4];"
                 : "=f"(v.x), "=f"(v.y), "=f"(v.z), "=f"(v.w) : "r"(a));
    return v;
}
__device__ __forceinline__ uint4 lds_u4(uint32_t a) {
    uint4 v;
    asm volatile("ld.shared.v4.b32 {%0,%1,%2,%3}, [%4];"
                 : "=r"(v.x), "=r"(v.y), "=r"(v.z), "=r"(v.w) : "r"(a));
    return v;
}

#define MMA16816(c, a0, a1, a2, a3, b0, b1) \
    asm volatile("mma.sync.aligned.m16n8k16.row.col.f32.bf16.bf16.f32 " \
        "{%0,%1,%2,%3}, {%4,%5,%6,%7}, {%8,%9}, {%0,%1,%2,%3};" \
        : "+f"((c)[0]), "+f"((c)[1]), "+f"((c)[2]), "+f"((c)[3]) \
        : "r"(a0), "r"(a1), "r"(a2), "r"(a3), "r"(b0), "r"(b1))

// ---------------------------------------------------------------------------
// Pack W (k-permuted fragment layout), rn split.
// ---------------------------------------------------------------------------
__device__ __forceinline__ float wval(const float* __restrict__ topW,
                                      const float* __restrict__ botW,
                                      int n, int k) {
    if (n < N_TOP) return topW[n * D + k];
    int m = n - 8;
    return botW[((m >> 4) * D + k) * N_CLS + (m & 15)];
}

__global__ void pack_kernel(const float* __restrict__ topW,
                            const float* __restrict__ topb,
                            const float* __restrict__ botW,
                            const float* __restrict__ botb) {
    int idx = blockIdx.x * blockDim.x + threadIdx.x;
    if (idx < NC) g_bc[idx] = (idx < N_TOP) ? topb[idx] : botb[idx - 8];
    if (idx >= KSTEPS * STEP_U4) return;

    int lane = idx & 31;
    int t    = (idx >> 5) % NTILES;
    int s    = idx / STEP_U4;
    int g = lane >> 2, q = lane & 3;
    int n  = t * 8 + g;
    int k0 = s * 16 + 4 * q;

    float x0 = wval(topW, botW, n, k0);
    float x1 = wval(topW, botW, n, k0 + 1);
    float x2 = wval(topW, botW, n, k0 + 2);
    float x3 = wval(topW, botW, n, k0 + 3);

    uint32_t h01, l01, h23, l23;
    rsplit2(x0, x1, h01, l01);
    rsplit2(x2, x3, h23, l23);
    g_Wp[idx] = make_uint4(h01, h23, l01, l23);
}

// ---------------------------------------------------------------------------
// Main kernel: per-warp cp.async pipeline (no barriers) + pass-major MMAs.
// Warp (wy=wid&3, wx=wid>>2): rows wy*32..+31; tiles wx*4..+3 (+tile 16 if wx==0).
// ---------------------------------------------------------------------------
__global__ __launch_bounds__(THREADS, 1)
void hier_mma_kernel(const float* __restrict__ A, float* __restrict__ out) {
    extern __shared__ char smem[];
    float* L = reinterpret_cast<float*>(smem);
    const uint32_t sb = smem_u32(smem);

    const int tid  = threadIdx.x;
    const int lane = tid & 31;
    const int wid  = tid >> 5;
    const int wy   = wid & 3;
    const int wx   = wid >> 2;
    const int g    = lane >> 2;
    const int q    = lane & 3;
    const int rowBase = blockIdx.x * BM;

    const int  tbase = wx * 4;
    const bool extra = (wx == 0);           // tile 16

    const uint32_t warpA = sb + (uint32_t)wid * (DEPTH * A_STAGE);
    const uint32_t warpB = sb + 16u * DEPTH * A_STAGE + (uint32_t)wid * (DEPTH * B_STAGE);

    // A: rows rowBase + wy*32 + g + {0,8,16,24}, cols 4q.. (+16 per kstep)
    const float* ap = A + (size_t)(rowBase + wy * 32 + g) * D + 4 * q;

    float acc[4][8], accE[8];
#pragma unroll
    for (int t = 0; t < 4; ++t)
#pragma unroll
        for (int j = 0; j < 8; ++j) acc[t][j] = 0.0f;
#pragma unroll
    for (int j = 0; j < 8; ++j) accE[j] = 0.0f;

    // issue copies for kstep s into stage st (each lane copies its OWN fragments)
    auto issue = [&](int s, int st) {
        const float* as = ap + (size_t)s * 16;
#pragma unroll
        for (int r = 0; r < 4; ++r)
            cpa16(warpA + st * A_STAGE + r * 512 + lane * 16, as + (size_t)r * 8 * D);
        const uint4* ws = g_Wp + (size_t)s * STEP_U4 + tbase * 32 + lane;
#pragma unroll
        for (int tt = 0; tt < 4; ++tt)
            cpa16(warpB + st * B_STAGE + tt * 512 + lane * 16, ws + tt * 32);
        if (extra)
            cpa16(warpB + st * B_STAGE + 2048 + lane * 16,
                  g_Wp + (size_t)s * STEP_U4 + 16 * 32 + lane);
    };

    // ---- prologue: ksteps 0,1 in flight ----
    issue(0, 0); CPA_COMMIT();
    issue(1, 1); CPA_COMMIT();

#pragma unroll 3
    for (int s = 0; s < KSTEPS; ++s) {
        // prefetch kstep s+2 (distinct stage from the one read below)
        if (s + 2 < KSTEPS) issue(s + 2, (s + 2) % DEPTH);
        CPA_COMMIT();          // always commit (possibly empty) to keep counts uniform
        CPA_WAIT2();           // kstep s copies complete (own-lane data only)

        const int st = s % DEPTH;
        const uint32_t aa = warpA + st * A_STAGE + lane * 16;
        float4 x0 = lds_f4(aa);
        float4 x1 = lds_f4(aa + 512);
        float4 x2 = lds_f4(aa + 1024);
        float4 x3 = lds_f4(aa + 1536);

        const uint32_t ba = warpB + st * B_STAGE + lane * 16;
        uint4 bc[4];
#pragma unroll
        for (int tt = 0; tt < 4; ++tt) bc[tt] = lds_u4(ba + tt * 512);
        uint4 bcE = extra ? lds_u4(ba + 2048) : bc[0];

        // split A into hi/lo fragments
        uint32_t ahi[8], alo[8];
        tsplit2(x0.x, x0.y, ahi[0], alo[0]);  tsplit2(x0.z, x0.w, ahi[1], alo[1]);
        tsplit2(x1.x, x1.y, ahi[2], alo[2]);  tsplit2(x1.z, x1.w, ahi[3], alo[3]);
        tsplit2(x2.x, x2.y, ahi[4], alo[4]);  tsplit2(x2.z, x2.w, ahi[5], alo[5]);
        tsplit2(x3.x, x3.y, ahi[6], alo[6]);  tsplit2(x3.z, x3.w, ahi[7], alo[7]);

        // pass-major MMA ordering: same-acc reuse distance ~9 MMAs
        // pass 0: hi * b.xy
#pragma unroll
        for (int tt = 0; tt < 4; ++tt)
            MMA16816(acc[tt],     ahi[0], ahi[2], ahi[1], ahi[3], bc[tt].x, bc[tt].y);
        if (extra) MMA16816(accE, ahi[0], ahi[2], ahi[1], ahi[3], bcE.x, bcE.y);
#pragma unroll
        for (int tt = 0; tt < 4; ++tt)
            MMA16816(acc[tt] + 4, ahi[4], ahi[6], ahi[5], ahi[7], bc[tt].x, bc[tt].y);
        if (extra) MMA16816(accE + 4, ahi[4], ahi[6], ahi[5], ahi[7], bcE.x, bcE.y);
        // pass 1: lo * b.xy
#pragma unroll
        for (int tt = 0; tt < 4; ++tt)
            MMA16816(acc[tt],     alo[0], alo[2], alo[1], alo[3], bc[tt].x, bc[tt].y);
        if (extra) MMA16816(accE, alo[0], alo[2], alo[1], alo[3], bcE.x, bcE.y);
#pragma unroll
        for (int tt = 0; tt < 4; ++tt)
            MMA16816(acc[tt] + 4, alo[4], alo[6], alo[5], alo[7], bc[tt].x, bc[tt].y);
        if (extra) MMA16816(accE + 4, alo[4], alo[6], alo[5], alo[7], bcE.x, bcE.y);
        // pass 2: hi * b.zw
#pragma unroll
        for (int tt = 0; tt < 4; ++tt)
            MMA16816(acc[tt],     ahi[0], ahi[2], ahi[1], ahi[3], bc[tt].z, bc[tt].w);
        if (extra) MMA16816(accE, ahi[0], ahi[2], ahi[1], ahi[3], bcE.z, bcE.w);
#pragma unroll
        for (int tt = 0; tt < 4; ++tt)
            MMA16816(acc[tt] + 4, ahi[4], ahi[6], ahi[5], ahi[7], bc[tt].z, bc[tt].w);
        if (extra) MMA16816(accE + 4, ahi[4], ahi[6], ahi[5], ahi[7], bcE.z, bcE.w);
    }

    __syncthreads();   // pipeline dead; smem becomes logits

    // ---- stage logits (+bias) into smem ----
#pragma unroll
    for (int tt = 0; tt < 5; ++tt) {
        const float* ac;
        int t;
        if (tt < 4) { ac = acc[tt]; t = tbase + tt; }
        else if (extra) { ac = accE; t = 16; }
        else break;
        int c = t * 8 + 2 * q;
        float b0 = g_bc[c], b1 = g_bc[c + 1];
#pragma unroll
        for (int h = 0; h < 2; ++h) {
            int r = wy * 32 + h * 16 + g;
            L[r * LPITCH + c]           = ac[4 * h + 0] + b0;
            L[r * LPITCH + c + 1]       = ac[4 * h + 1] + b1;
            L[(r + 8) * LPITCH + c]     = ac[4 * h + 2] + b0;
            L[(r + 8) * LPITCH + c + 1] = ac[4 * h + 3] + b1;
        }
    }
    __syncthreads();

    // ---- per-row: sigmoid gate + 8x softmax(16), in place ----
    if (tid < BM) {
        float* Lr = L + tid * LPITCH;
#pragma unroll
        for (int t = 0; t < N_TOP; ++t) {
            float gate = 1.0f / (1.0f + __expf(-Lr[t]));
            float* gr = Lr + 8 + t * N_CLS;
            float m = gr[0];
#pragma unroll
            for (int c = 1; c < N_CLS; ++c) m = fmaxf(m, gr[c]);
            float e[N_CLS];
            float sum = 0.0f;
#pragma unroll
            for (int c = 0; c < N_CLS; ++c) { e[c] = __expf(gr[c] - m); sum += e[c]; }
            float inv = gate / sum;
#pragma unroll
            for (int c = 0; c < N_CLS; ++c) gr[c] = e[c] * inv;
        }
    }
    __syncthreads();

    // ---- coalesced writeback 128x128 ----
    for (int idx = tid; idx < BM * N_OUT; idx += THREADS) {
        int r = idx >> 7, c = idx & 127;
        out[(size_t)(rowBase + r) * N_OUT + c] = L[r * LPITCH + 8 + c];
    }
}

// ---------------------------------------------------------------------------
extern "C" void kernel_launch(void* const* d_in, const int* in_sizes, int n_in,
                              void* d_out, int out_size) {
    const float* features = (const float*)d_in[0];
    const float* top_W    = (const float*)d_in[1];
    const float* top_b    = (const float*)d_in[2];
    const float* bottom_W = (const float*)d_in[3];
    const float* bottom_b = (const float*)d_in[4];
    float* out = (float*)d_out;

    {
        int total = KSTEPS * STEP_U4;
        int threads = 256;
        pack_kernel<<<(total + threads - 1) / threads, threads>>>(
            top_W, top_b, bottom_W, bottom_b);
    }
    cudaFuncSetAttribute(hier_mma_kernel,
                         cudaFuncAttributeMaxDynamicSharedMemorySize, SMEM);
    hier_mma_kernel<<<B_ROWS / BM, THREADS, SMEM>>>(features, out);
}